// round 1
// baseline (speedup 1.0000x reference)
#include <cuda_runtime.h>
#include <math.h>

// Problem constants
#define BB    16
#define TT    256
#define DD    512
#define LL1   51
#define MM    (BB*TT)        // 4096
#define LL2   (LL1*LL1)      // 2601
#define LOG2PI 1.8378770664093453f

// ---------------- scratch (device globals; no allocation allowed) -----------
__device__ __align__(256) float g_sw  [MM*LL1];
__device__ __align__(256) float g_smu [MM*LL1];
__device__ __align__(256) float g_svar[MM*LL1];          // raw (pre exp/clip)
__device__ __align__(256) float g_tw  [MM*LL2];
__device__ __align__(256) float g_tmu [MM*LL2*2];
__device__ __align__(256) float g_tvar[MM*LL2*4];        // raw 2x2

// ---------------- fp32 SGEMM 128x128x8, 256 threads, bias epilogue ----------
__global__ __launch_bounds__(256) void sgemm_bias_kernel(
    const float* __restrict__ A,      // M x K row-major (M=4096, K=512)
    const float* __restrict__ Bw,     // K x N row-major
    const float* __restrict__ bias,   // N
    float* __restrict__ C,            // M x N row-major
    int N)
{
    const int K = DD;
    __shared__ float As[8][128];
    __shared__ float Bs[8][128];

    int tid  = threadIdx.x;
    int brow = blockIdx.y * 128;
    int bcol = blockIdx.x * 128;

    // A tile load mapping: float4 per thread
    int arow = tid >> 1;            // 0..127
    int acol = (tid & 1) * 4;       // 0 or 4
    // B tile load mapping: 4 scalars per thread (row stride N may be odd)
    int bkr  = tid >> 5;            // 0..7
    int bct  = (tid & 31) * 4;      // 0..124

    int ty = tid >> 4;              // 0..15 -> rows
    int tx = tid & 15;              // 0..15 -> cols

    float acc[8][8];
    #pragma unroll
    for (int u = 0; u < 8; u++)
        #pragma unroll
        for (int v = 0; v < 8; v++) acc[u][v] = 0.f;

    const float* Aptr = A + (brow + arow) * K + acol;

    for (int k0 = 0; k0 < K; k0 += 8) {
        float4 av = *(const float4*)(Aptr + k0);
        As[acol + 0][arow] = av.x;
        As[acol + 1][arow] = av.y;
        As[acol + 2][arow] = av.z;
        As[acol + 3][arow] = av.w;
        int gk = k0 + bkr;
        #pragma unroll
        for (int u = 0; u < 4; u++) {
            int c = bcol + bct + u;
            Bs[bkr][bct + u] = (c < N) ? Bw[gk * N + c] : 0.f;
        }
        __syncthreads();
        #pragma unroll
        for (int k = 0; k < 8; k++) {
            float4 a0 = *(const float4*)&As[k][ty * 8];
            float4 a1 = *(const float4*)&As[k][ty * 8 + 4];
            float4 b0 = *(const float4*)&Bs[k][tx * 8];
            float4 b1 = *(const float4*)&Bs[k][tx * 8 + 4];
            float ar[8] = {a0.x,a0.y,a0.z,a0.w,a1.x,a1.y,a1.z,a1.w};
            float br[8] = {b0.x,b0.y,b0.z,b0.w,b1.x,b1.y,b1.z,b1.w};
            #pragma unroll
            for (int u = 0; u < 8; u++)
                #pragma unroll
                for (int v = 0; v < 8; v++)
                    acc[u][v] = fmaf(ar[u], br[v], acc[u][v]);
        }
        __syncthreads();
    }

    #pragma unroll
    for (int u = 0; u < 8; u++) {
        int r = brow + ty * 8 + u;
        #pragma unroll
        for (int v = 0; v < 8; v++) {
            int c = bcol + tx * 8 + v;
            if (c < N) C[(size_t)r * N + c] = acc[u][v] + bias[c];
        }
    }
}

// ---------------- merge2x2 (faithful to reference math, fp32) ---------------
__device__ __forceinline__ float clip1(float v) {
    return fminf(fmaxf(v, -1.0f), 1.0f);
}

__device__ __forceinline__ void merge2x2(
    float tmu0, float tmu1, float tv00, float tv01, float tv11,
    float nmu, float nvar, bool child,
    float& zeta, float& mu_new, float& var_new)
{
    float det = tv00 * tv11 - tv01 * tv01;
    float a  = tv11 / det;
    float bo = -tv01 / det;
    float dd = tv00 / det;
    float e0 = a  * tmu0 + bo * tmu1;
    float e1 = bo * tmu0 + dd * tmu1;
    float quad1 = e0 * e0 * tv00 + 2.0f * e0 * e1 * tv01 + e1 * e1 * tv11;
    float zeta1 = -0.5f * (2.0f * LOG2PI + logf(det) + quad1);
    float l2   = 1.0f / nvar;
    float eta2 = nmu * l2;
    float zeta2 = -0.5f * (LOG2PI + logf(nvar) + nmu * nmu * l2);
    float den, keep, es, la;
    if (child) { den = dd + l2; keep = e0; es = e1 + eta2; la = a  - bo * bo / den; }
    else       { den = a  + l2; keep = e1; es = e0 + eta2; la = dd - bo * bo / den; }
    float eta_new = keep - bo / den * es;
    var_new = 1.0f / la;
    mu_new  = var_new * eta_new;
    float zeta_merge = -0.5f * (LOG2PI - logf(den) + es * es / den);
    float zeta_new   = -0.5f * (LOG2PI - logf(la)  + eta_new * eta_new * var_new);
    zeta = zeta1 + zeta2 - zeta_merge - zeta_new;
}

// Load + transform t-potential at (row, chain)
__device__ __forceinline__ void load_t(
    int row, int chain,
    float& tw, float& tm0, float& tm1,
    float& tv00, float& tv01, float& tv11)
{
    tw = g_tw[(size_t)row * LL2 + chain];
    float2 tm = *(const float2*)&g_tmu[(size_t)row * (2 * LL2) + chain * 2];
    float4 tv = *(const float4*)&g_tvar[(size_t)row * (4 * LL2) + chain * 4];
    tm0 = tm.x; tm1 = tm.y;
    float d0 = expf(clip1(tv.x));          // t_raw[...,0,0]
    float d1 = expf(clip1(tv.w));          // t_raw[...,1,1]
    float off = 0.9f * tanhf(0.5f * (tv.y + tv.z)) * sqrtf(d0 * d1);
    tv00 = d0; tv01 = off; tv11 = d1;
}

// ---------------- scan over T: one thread per (b, i, j) chain ---------------
__global__ __launch_bounds__(256) void scan_kernel(float* __restrict__ out)
{
    int chain = blockIdx.x * blockDim.x + threadIdx.x;
    if (chain >= LL2) return;
    int b = blockIdx.y;
    int j = chain % LL1;

    // ---- t = 0: merge child with s@0, then parent with t@1 ----
    int row0 = b * TT;
    float tw0, tm0, tm1, tv00, tv01, tv11;
    load_t(row0, chain, tw0, tm0, tm1, tv00, tv01, tv11);
    float sw0   = g_sw  [row0 * LL1 + j];
    float smu0  = g_smu [row0 * LL1 + j];
    float svar0 = expf(clip1(g_svar[row0 * LL1 + j]));

    float sc0, mu_c, var_c;
    merge2x2(tm0, tm1, tv00, tv01, tv11, smu0, svar0, true, sc0, mu_c, var_c);

    int row1 = row0 + 1;
    float tw1, um0, um1, uv00, uv01, uv11;
    load_t(row1, chain, tw1, um0, um1, uv00, uv01, uv11);
    float sp0, mu_p, var_p;
    merge2x2(um0, um1, uv00, uv01, uv11, mu_c, var_c, false, sp0, mu_p, var_p);

    out[(size_t)row0 * LL2 + chain] = sc0 + sp0 + tw0 + sw0;

    // ---- t = 1..T-1: scan steps ----
    for (int t = 1; t < TT; t++) {
        int row = b * TT + t;
        float tw, m0, m1, v00, v01, v11;
        load_t(row, chain, tw, m0, m1, v00, v01, v11);
        float sw   = g_sw  [row * LL1 + j];
        float smu  = g_smu [row * LL1 + j];
        float svar = expf(clip1(g_svar[row * LL1 + j]));

        float vsum = var_p + svar;
        float logv = logf(vsum);
        float inv  = 1.0f / vsum;
        float diff = mu_p - smu;
        float scale_c = -0.5f * (LOG2PI + logv + diff * diff * inv);
        float mu_c2  = (mu_p * svar + smu * var_p) * inv;
        float var_c2 = vsum - 0.5f * logv;

        float scale_p, mu_n, var_n;
        merge2x2(m0, m1, v00, v01, v11, mu_c2, var_c2, false, scale_p, mu_n, var_n);
        mu_p = mu_n; var_p = var_n;

        out[(size_t)row * LL2 + chain] = scale_c + scale_p + tw + sw;
    }
}

// ---------------- launch -----------------------------------------------------
extern "C" void kernel_launch(void* const* d_in, const int* in_sizes, int n_in,
                              void* d_out, int out_size)
{
    const float* x      = (const float*)d_in[0];
    const float* Ws_w   = (const float*)d_in[1];
    const float* bs_w   = (const float*)d_in[2];
    const float* Ws_mu  = (const float*)d_in[3];
    const float* bs_mu  = (const float*)d_in[4];
    const float* Ws_var = (const float*)d_in[5];
    const float* bs_var = (const float*)d_in[6];
    const float* Wt_w   = (const float*)d_in[7];
    const float* bt_w   = (const float*)d_in[8];
    const float* Wt_mu  = (const float*)d_in[9];
    const float* bt_mu  = (const float*)d_in[10];
    const float* Wt_var = (const float*)d_in[11];
    const float* bt_var = (const float*)d_in[12];
    float* out = (float*)d_out;

    float *p_sw, *p_smu, *p_svar, *p_tw, *p_tmu, *p_tvar;
    cudaGetSymbolAddress((void**)&p_sw,   g_sw);
    cudaGetSymbolAddress((void**)&p_smu,  g_smu);
    cudaGetSymbolAddress((void**)&p_svar, g_svar);
    cudaGetSymbolAddress((void**)&p_tw,   g_tw);
    cudaGetSymbolAddress((void**)&p_tmu,  g_tmu);
    cudaGetSymbolAddress((void**)&p_tvar, g_tvar);

    dim3 blk(256);
    auto grid_for = [](int N) { return dim3((N + 127) / 128, MM / 128); };

    sgemm_bias_kernel<<<grid_for(LL1),     blk>>>(x, Ws_w,   bs_w,   p_sw,   LL1);
    sgemm_bias_kernel<<<grid_for(LL1),     blk>>>(x, Ws_mu,  bs_mu,  p_smu,  LL1);
    sgemm_bias_kernel<<<grid_for(LL1),     blk>>>(x, Ws_var, bs_var, p_svar, LL1);
    sgemm_bias_kernel<<<grid_for(LL2),     blk>>>(x, Wt_w,   bt_w,   p_tw,   LL2);
    sgemm_bias_kernel<<<grid_for(LL2 * 2), blk>>>(x, Wt_mu,  bt_mu,  p_tmu,  LL2 * 2);
    sgemm_bias_kernel<<<grid_for(LL2 * 4), blk>>>(x, Wt_var, bt_var, p_tvar, LL2 * 4);

    dim3 sgrid((LL2 + 255) / 256, BB);
    scan_kernel<<<sgrid, blk>>>(out);
}

// round 3
// speedup vs baseline: 2.6241x; 2.6241x over previous
#include <cuda_runtime.h>
#include <cuda_bf16.h>
#include <math.h>
#include <stdint.h>

// ---------------- problem constants ----------------
#define BB 16
#define TT 256
#define DD 512
#define LL1 51
#define MM (BB*TT)            // 4096
#define LL2 (LL1*LL1)         // 2601
#define KP 1536               // split-K: [x_hi | x_hi | x_lo] * [W_hi ; W_lo ; W_hi]
#define KC 64
#define NCH (KP/KC)           // 24
#define LOG2PI 1.8378770664093453f

// padded N (multiples of 128) per GEMM
#define NP_S    128
#define NP_TW   2688          // >= 2601
#define NP_TMU  5248          // >= 5202
#define NP_TVAR 10496         // >= 10404
#define BP_ROWS (3*NP_S + NP_TW + NP_TMU + NP_TVAR)   // 18816

// ---------------- scratch (device globals) ----------------
__device__ __align__(256) __nv_bfloat16 g_Ap[(size_t)MM*KP];
__device__ __align__(256) __nv_bfloat16 g_Bp[(size_t)BP_ROWS*KP];
__device__ __align__(256) float g_sw  [MM*LL1];
__device__ __align__(256) float g_smu [MM*LL1];
__device__ __align__(256) float g_svar[MM*LL1];              // exp(clip()) pre-applied
__device__ __align__(256) float g_tw  [(size_t)MM*LL2];
__device__ __align__(256) float g_tmu [(size_t)MM*LL2*2];
__device__ __align__(256) float g_tvar[(size_t)MM*LL2*4];    // (d0, off, d1, 0) pre-applied

// ---------------- PTX helpers (Ampere-baseline only; no tcgen05) ------------
__device__ __forceinline__ uint32_t smem_u32(const void* p) {
    uint32_t a;
    asm("{ .reg .u64 t; cvta.to.shared.u64 t, %1; cvt.u32.u64 %0, t; }" : "=r"(a) : "l"(p));
    return a;
}
__device__ __forceinline__ void cp_async16(uint32_t dst, const void* src) {
    asm volatile("cp.async.cg.shared.global [%0], [%1], 16;" :: "r"(dst), "l"(src));
}
#define CP_COMMIT() asm volatile("cp.async.commit_group;" ::: "memory")
#define CP_WAIT(n)  asm volatile("cp.async.wait_group %0;" :: "n"(n) : "memory")

__device__ __forceinline__ void ldmx4(uint32_t* r, uint32_t addr) {
    asm volatile("ldmatrix.sync.aligned.m8n8.x4.shared.b16 {%0,%1,%2,%3}, [%4];"
        : "=r"(r[0]), "=r"(r[1]), "=r"(r[2]), "=r"(r[3]) : "r"(addr));
}
__device__ __forceinline__ void mma16816(float* c, const uint32_t* a, uint32_t b0, uint32_t b1) {
    asm volatile("mma.sync.aligned.m16n8k16.row.col.f32.bf16.bf16.f32 "
        "{%0,%1,%2,%3}, {%4,%5,%6,%7}, {%8,%9}, {%0,%1,%2,%3};"
        : "+f"(c[0]), "+f"(c[1]), "+f"(c[2]), "+f"(c[3])
        : "r"(a[0]), "r"(a[1]), "r"(a[2]), "r"(a[3]), "r"(b0), "r"(b1));
}

// ---------------- prep: split x into A' = [hi | hi | lo] ----------------
__global__ void prep_x(const float* __restrict__ x) {
    int t = blockIdx.x * blockDim.x + threadIdx.x;
    if (t >= MM * DD) return;
    int m = t >> 9;
    int k = t & 511;
    float v = x[t];
    __nv_bfloat16 hi = __float2bfloat16(v);
    __nv_bfloat16 lo = __float2bfloat16(v - __bfloat162float(hi));
    size_t base = (size_t)m * KP + k;
    g_Ap[base]        = hi;
    g_Ap[base + 512]  = hi;
    g_Ap[base + 1024] = lo;
}

// ---------------- prep: transpose+split W (KxN -> N-major [hi;lo;hi]) -------
__global__ void prep_w(const float* __restrict__ W, int Ntrue, int rowOff) {
    __shared__ float tile[32][33];
    int tx = threadIdx.x, ty = threadIdx.y;   // (32, 8)
    int n = blockIdx.x * 32 + tx;
    #pragma unroll
    for (int i = 0; i < 4; i++) {
        int k = blockIdx.y * 32 + ty + i * 8;
        tile[ty + i * 8][tx] = (n < Ntrue) ? W[(size_t)k * Ntrue + n] : 0.f;
    }
    __syncthreads();
    #pragma unroll
    for (int i = 0; i < 4; i++) {
        int n2 = blockIdx.x * 32 + ty + i * 8;
        int k2 = blockIdx.y * 32 + tx;
        float v = tile[tx][ty + i * 8];
        __nv_bfloat16 hi = __float2bfloat16(v);
        __nv_bfloat16 lo = __float2bfloat16(v - __bfloat162float(hi));
        __nv_bfloat16* row = g_Bp + (size_t)(rowOff + n2) * KP;
        row[k2]        = hi;
        row[512 + k2]  = lo;
        row[1024 + k2] = hi;
    }
}

// ---------------- HMMA GEMM: 128x128 CTA, KC=64, double-buffered cp.async ---
// SMEM per buffer: A 128x72 bf16 (18432 B) + B 128x72 bf16 (18432 B) = 36864 B
// Two buffers = 73728 B; epilogue staging reuses as 128x132 fp32 (67584 B)
#define TILE_STRIDE 72
#define BUF_BYTES 36864
#define SMEM_BYTES 73728
#define STG_STRIDE 132

__device__ __forceinline__ void issue_tile(uint32_t dstBase,
                                           const __nv_bfloat16* __restrict__ src,
                                           int row0, int kc, int tid) {
    #pragma unroll
    for (int i = 0; i < 4; i++) {
        int ci  = i * 256 + tid;          // 0..1023
        int r   = ci >> 3;                // 0..127
        int c16 = ci & 7;                 // 16B chunk within 128B row
        uint32_t dst = dstBase + (uint32_t)(r * (TILE_STRIDE * 2) + c16 * 16);
        cp_async16(dst, src + (size_t)(row0 + r) * KP + kc + c16 * 8);
    }
}

__global__ void __launch_bounds__(256) gemm_tc(
    int rowOff, const float* __restrict__ bias,
    float* __restrict__ C, int Ntrue, int mode)
{
    extern __shared__ char smem[];
    uint32_t sbase = smem_u32(smem);
    int tid = threadIdx.x, wid = tid >> 5, lane = tid & 31;
    int m0 = blockIdx.x * 128;
    int n0 = blockIdx.y * 128;
    int brow = rowOff + n0;

    int wm = (wid & 3) * 32;      // warp row offset
    int wn = (wid >> 2) * 64;     // warp col offset
    int lr = lane & 15;
    int lc = (lane >> 4) * 8;

    float acc[2][8][4];
    #pragma unroll
    for (int mi = 0; mi < 2; mi++)
        #pragma unroll
        for (int ni = 0; ni < 8; ni++)
            #pragma unroll
            for (int q = 0; q < 4; q++) acc[mi][ni][q] = 0.f;

    // prologue: chunk 0 -> buf 0
    issue_tile(sbase, g_Ap, m0, 0, tid);
    issue_tile(sbase + 18432, g_Bp, brow, 0, tid);
    CP_COMMIT();

    for (int c = 0; c < NCH; c++) {
        int buf = c & 1;
        if (c + 1 < NCH) {
            uint32_t nbBase = sbase + (uint32_t)((buf ^ 1) * BUF_BYTES);
            issue_tile(nbBase, g_Ap, m0, (c + 1) * KC, tid);
            issue_tile(nbBase + 18432, g_Bp, brow, (c + 1) * KC, tid);
            CP_COMMIT();
            CP_WAIT(1);
        } else {
            CP_WAIT(0);
        }
        __syncthreads();

        uint32_t aBase = sbase + (uint32_t)(buf * BUF_BYTES);
        uint32_t bBase = aBase + 18432;
        #pragma unroll
        for (int ks = 0; ks < 4; ks++) {
            uint32_t af[2][4];
            #pragma unroll
            for (int mi = 0; mi < 2; mi++)
                ldmx4(af[mi], aBase + (uint32_t)(((wm + mi * 16 + lr) * TILE_STRIDE
                                                  + ks * 16 + lc) * 2));
            uint32_t bf[4][4];
            #pragma unroll
            for (int nb = 0; nb < 4; nb++)
                ldmx4(bf[nb], bBase + (uint32_t)(((wn + nb * 16 + lr) * TILE_STRIDE
                                                  + ks * 16 + lc) * 2));
            #pragma unroll
            for (int mi = 0; mi < 2; mi++)
                #pragma unroll
                for (int nb = 0; nb < 4; nb++) {
                    mma16816(acc[mi][nb * 2 + 0], af[mi], bf[nb][0], bf[nb][2]);
                    mma16816(acc[mi][nb * 2 + 1], af[mi], bf[nb][1], bf[nb][3]);
                }
        }
        __syncthreads();
    }

    // ---- epilogue: stage to SMEM (fp32, 128x132) ----
    float* stage = (float*)smem;
    int gr = lane >> 2;            // 0..7
    int gc = (lane & 3) * 2;       // 0,2,4,6
    #pragma unroll
    for (int mi = 0; mi < 2; mi++)
        #pragma unroll
        for (int ni = 0; ni < 8; ni++) {
            int row = wm + mi * 16 + gr;
            int col = wn + ni * 8 + gc;
            *(float2*)&stage[row * STG_STRIDE + col] =
                make_float2(acc[mi][ni][0], acc[mi][ni][1]);
            *(float2*)&stage[(row + 8) * STG_STRIDE + col] =
                make_float2(acc[mi][ni][2], acc[mi][ni][3]);
        }
    __syncthreads();

    if (mode == 2) {
        // 4-col groups: (d0, off, d1, 0)
        for (int g = tid; g < 128 * 32; g += 256) {
            int row = g >> 5, grp = g & 31;
            int n = n0 + grp * 4;
            if (n < Ntrue) {
                const float* s = &stage[row * STG_STRIDE + grp * 4];
                float v0 = s[0] + bias[n];
                float v1 = s[1] + bias[n + 1];
                float v2 = s[2] + bias[n + 2];
                float v3 = s[3] + bias[n + 3];
                float d0 = expf(fminf(fmaxf(v0, -1.f), 1.f));
                float d1 = expf(fminf(fmaxf(v3, -1.f), 1.f));
                float off = 0.9f * tanhf(0.5f * (v1 + v2)) * sqrtf(d0 * d1);
                *(float4*)&C[(size_t)(m0 + row) * Ntrue + n] =
                    make_float4(d0, off, d1, 0.f);
            }
        }
    } else if (mode == 1) {
        for (int i = tid; i < 128 * 128; i += 256) {
            int row = i >> 7, col = i & 127;
            int n = n0 + col;
            if (n < Ntrue) {
                float v = stage[row * STG_STRIDE + col] + bias[n];
                C[(size_t)(m0 + row) * Ntrue + n] = expf(fminf(fmaxf(v, -1.f), 1.f));
            }
        }
    } else {
        for (int i = tid; i < 128 * 128; i += 256) {
            int row = i >> 7, col = i & 127;
            int n = n0 + col;
            if (n < Ntrue)
                C[(size_t)(m0 + row) * Ntrue + n] = stage[row * STG_STRIDE + col] + bias[n];
        }
    }
}

// ---------------- scan (transforms pre-applied in GEMM epilogue) ------------
__device__ __forceinline__ void load_t2(int row, int chain,
    float& tw, float& m0, float& m1, float& v00, float& v01, float& v11)
{
    size_t idx = (size_t)row * LL2 + chain;
    tw = g_tw[idx];
    float2 tm = *(const float2*)&g_tmu[idx * 2];
    float4 tv = *(const float4*)&g_tvar[idx * 4];
    m0 = tm.x; m1 = tm.y;
    v00 = tv.x; v01 = tv.y; v11 = tv.z;
}

__device__ __forceinline__ void merge2x2(
    float tmu0, float tmu1, float tv00, float tv01, float tv11,
    float nmu, float nvar, bool child,
    float& zeta, float& mu_new, float& var_new)
{
    float det  = tv00 * tv11 - tv01 * tv01;
    float idet = __fdividef(1.f, det);
    float a  = tv11 * idet;
    float bo = -tv01 * idet;
    float dd = tv00 * idet;
    float e0 = a  * tmu0 + bo * tmu1;
    float e1 = bo * tmu0 + dd * tmu1;
    float quad1 = e0 * e0 * tv00 + 2.f * e0 * e1 * tv01 + e1 * e1 * tv11;
    float zeta1 = -0.5f * (2.f * LOG2PI + __logf(det) + quad1);
    float l2   = __fdividef(1.f, nvar);
    float eta2 = nmu * l2;
    float zeta2 = -0.5f * (LOG2PI + __logf(nvar) + nmu * nmu * l2);
    float den, keep, es, la, iden;
    if (child) { den = dd + l2; iden = __fdividef(1.f, den); keep = e0; es = e1 + eta2; la = a  - bo * bo * iden; }
    else       { den = a  + l2; iden = __fdividef(1.f, den); keep = e1; es = e0 + eta2; la = dd - bo * bo * iden; }
    float eta_new = keep - bo * iden * es;
    var_new = __fdividef(1.f, la);
    mu_new  = var_new * eta_new;
    float zm = -0.5f * (LOG2PI - __logf(den) + es * es * iden);
    float zn = -0.5f * (LOG2PI - __logf(la)  + eta_new * eta_new * var_new);
    zeta = zeta1 + zeta2 - zm - zn;
}

__global__ __launch_bounds__(256) void scan_kernel(float* __restrict__ out)
{
    int chain = blockIdx.x * blockDim.x + threadIdx.x;
    if (chain >= LL2) return;
    int b = blockIdx.y;
    int j = chain % LL1;

    int row0 = b * TT;
    float tw0, tm0, tm1, tv00, tv01, tv11;
    load_t2(row0, chain, tw0, tm0, tm1, tv00, tv01, tv11);
    float sw0   = g_sw  [row0 * LL1 + j];
    float smu0  = g_smu [row0 * LL1 + j];
    float svar0 = g_svar[row0 * LL1 + j];

    float sc0, mu_c, var_c;
    merge2x2(tm0, tm1, tv00, tv01, tv11, smu0, svar0, true, sc0, mu_c, var_c);

    float tw1, um0, um1, uv00, uv01, uv11;
    load_t2(row0 + 1, chain, tw1, um0, um1, uv00, uv01, uv11);
    float sp0, mu_p, var_p;
    merge2x2(um0, um1, uv00, uv01, uv11, mu_c, var_c, false, sp0, mu_p, var_p);

    out[(size_t)row0 * LL2 + chain] = sc0 + sp0 + tw0 + sw0;

    for (int t = 1; t < TT; t++) {
        int row = b * TT + t;
        float tw, m0, m1, v00, v01, v11;
        load_t2(row, chain, tw, m0, m1, v00, v01, v11);
        float sw   = g_sw  [row * LL1 + j];
        float smu  = g_smu [row * LL1 + j];
        float svar = g_svar[row * LL1 + j];

        float vsum = var_p + svar;
        float logv = __logf(vsum);
        float inv  = __fdividef(1.f, vsum);
        float diff = mu_p - smu;
        float scale_c = -0.5f * (LOG2PI + logv + diff * diff * inv);
        float mu_c2  = (mu_p * svar + smu * var_p) * inv;
        float var_c2 = vsum - 0.5f * logv;

        float scale_p, mu_n, var_n;
        merge2x2(m0, m1, v00, v01, v11, mu_c2, var_c2, false, scale_p, mu_n, var_n);
        mu_p = mu_n; var_p = var_n;

        out[(size_t)row * LL2 + chain] = scale_c + scale_p + tw + sw;
    }
}

// ---------------- launch ----------------
extern "C" void kernel_launch(void* const* d_in, const int* in_sizes, int n_in,
                              void* d_out, int out_size)
{
    const float* x      = (const float*)d_in[0];
    const float* Ws_w   = (const float*)d_in[1];
    const float* bs_w   = (const float*)d_in[2];
    const float* Ws_mu  = (const float*)d_in[3];
    const float* bs_mu  = (const float*)d_in[4];
    const float* Ws_var = (const float*)d_in[5];
    const float* bs_var = (const float*)d_in[6];
    const float* Wt_w   = (const float*)d_in[7];
    const float* bt_w   = (const float*)d_in[8];
    const float* Wt_mu  = (const float*)d_in[9];
    const float* bt_mu  = (const float*)d_in[10];
    const float* Wt_var = (const float*)d_in[11];
    const float* bt_var = (const float*)d_in[12];
    float* out = (float*)d_out;

    float *p_sw, *p_smu, *p_svar, *p_tw, *p_tmu, *p_tvar;
    cudaGetSymbolAddress((void**)&p_sw,   g_sw);
    cudaGetSymbolAddress((void**)&p_smu,  g_smu);
    cudaGetSymbolAddress((void**)&p_svar, g_svar);
    cudaGetSymbolAddress((void**)&p_tw,   g_tw);
    cudaGetSymbolAddress((void**)&p_tmu,  g_tmu);
    cudaGetSymbolAddress((void**)&p_tvar, g_tvar);

    cudaFuncSetAttribute(gemm_tc, cudaFuncAttributeMaxDynamicSharedMemorySize, SMEM_BYTES);

    // prep
    prep_x<<<(MM * DD) / 256, 256>>>(x);
    dim3 wblk(32, 8);
    prep_w<<<dim3(NP_S    / 32, 16), wblk>>>(Ws_w,   LL1,     0);
    prep_w<<<dim3(NP_S    / 32, 16), wblk>>>(Ws_mu,  LL1,     NP_S);
    prep_w<<<dim3(NP_S    / 32, 16), wblk>>>(Ws_var, LL1,     2 * NP_S);
    prep_w<<<dim3(NP_TW   / 32, 16), wblk>>>(Wt_w,   LL2,     3 * NP_S);
    prep_w<<<dim3(NP_TMU  / 32, 16), wblk>>>(Wt_mu,  LL2 * 2, 3 * NP_S + NP_TW);
    prep_w<<<dim3(NP_TVAR / 32, 16), wblk>>>(Wt_var, LL2 * 4, 3 * NP_S + NP_TW + NP_TMU);

    // HMMA GEMMs
    gemm_tc<<<dim3(32, 1),             256, SMEM_BYTES>>>(0,        bs_w,   p_sw,   LL1,     0);
    gemm_tc<<<dim3(32, 1),             256, SMEM_BYTES>>>(NP_S,     bs_mu,  p_smu,  LL1,     0);
    gemm_tc<<<dim3(32, 1),             256, SMEM_BYTES>>>(2 * NP_S, bs_var, p_svar, LL1,     1);
    gemm_tc<<<dim3(32, NP_TW   / 128), 256, SMEM_BYTES>>>(3 * NP_S,                  bt_w,   p_tw,   LL2,     0);
    gemm_tc<<<dim3(32, NP_TMU  / 128), 256, SMEM_BYTES>>>(3 * NP_S + NP_TW,          bt_mu,  p_tmu,  LL2 * 2, 0);
    gemm_tc<<<dim3(32, NP_TVAR / 128), 256, SMEM_BYTES>>>(3 * NP_S + NP_TW + NP_TMU, bt_var, p_tvar, LL2 * 4, 2);

    // scan
    scan_kernel<<<dim3((LL2 + 255) / 256, BB), 256>>>(out);
}

// round 4
// speedup vs baseline: 3.5527x; 1.3539x over previous
#include <cuda_runtime.h>
#include <cuda_bf16.h>
#include <math.h>
#include <stdint.h>

// ---------------- problem constants ----------------
#define BB 16
#define TT 256
#define DD 512
#define LL1 51
#define MM (BB*TT)            // 4096
#define LL2 (LL1*LL1)         // 2601
#define KP 1536               // split-K: [x_hi | x_hi | x_lo] * [W_hi ; W_lo ; W_hi]
#define KC 64
#define NCH (KP/KC)           // 24
#define LOG2PI 1.8378770664093453f

// planar output layout (all offsets multiples of 128)
#define NP_CH  2688           // chain pad (>= 2601)
#define PS_W   0
#define PS_MU  128
#define PS_VAR 256
#define PT_W   384
#define PT_MU0 (PT_W  + NP_CH)   // 3072
#define PT_MU1 (PT_MU0 + NP_CH)  // 5760
#define PT_D0  (PT_MU1 + NP_CH)  // 8448
#define PT_SUM (PT_D0 + NP_CH)   // 11136
#define PT_D1  (PT_SUM + NP_CH)  // 13824
#define NTOT   (PT_D1 + NP_CH)   // 16512
#define NTILES (NTOT/128)        // 129

// ---------------- scratch (device globals) ----------------
__device__ __align__(256) __nv_bfloat16 g_Ap[(size_t)MM*KP];
__device__ __align__(256) __nv_bfloat16 g_Bp[(size_t)NTOT*KP];
__device__ __align__(256) float g_bias[NTOT];
__device__ __align__(256) float g_C[(size_t)MM*NTOT];

// ---------------- PTX helpers ----------------
__device__ __forceinline__ uint32_t smem_u32(const void* p) {
    uint32_t a;
    asm("{ .reg .u64 t; cvta.to.shared.u64 t, %1; cvt.u32.u64 %0, t; }" : "=r"(a) : "l"(p));
    return a;
}
__device__ __forceinline__ void cp_async16(uint32_t dst, const void* src) {
    asm volatile("cp.async.cg.shared.global [%0], [%1], 16;" :: "r"(dst), "l"(src));
}
#define CP_COMMIT() asm volatile("cp.async.commit_group;" ::: "memory")
#define CP_WAIT(n)  asm volatile("cp.async.wait_group %0;" :: "n"(n) : "memory")

__device__ __forceinline__ void ldmx4(uint32_t* r, uint32_t addr) {
    asm volatile("ldmatrix.sync.aligned.m8n8.x4.shared.b16 {%0,%1,%2,%3}, [%4];"
        : "=r"(r[0]), "=r"(r[1]), "=r"(r[2]), "=r"(r[3]) : "r"(addr));
}
__device__ __forceinline__ void mma16816(float* c, const uint32_t* a, uint32_t b0, uint32_t b1) {
    asm volatile("mma.sync.aligned.m16n8k16.row.col.f32.bf16.bf16.f32 "
        "{%0,%1,%2,%3}, {%4,%5,%6,%7}, {%8,%9}, {%0,%1,%2,%3};"
        : "+f"(c[0]), "+f"(c[1]), "+f"(c[2]), "+f"(c[3])
        : "r"(a[0]), "r"(a[1]), "r"(a[2]), "r"(a[3]), "r"(b0), "r"(b1));
}

// ---------------- prep: split x into A' = [hi | hi | lo] ----------------
__global__ void prep_x(const float* __restrict__ x) {
    int t = blockIdx.x * blockDim.x + threadIdx.x;
    if (t >= MM * DD) return;
    int m = t >> 9;
    int k = t & 511;
    float v = x[t];
    __nv_bfloat16 hi = __float2bfloat16(v);
    __nv_bfloat16 lo = __float2bfloat16(v - __bfloat162float(hi));
    size_t base = (size_t)m * KP + k;
    g_Ap[base]        = hi;
    g_Ap[base + 512]  = hi;
    g_Ap[base + 1024] = lo;
}

// ---------------- prep: generic column-gather transpose+split ----------------
// dst row (dstOff+n) <- src column (n*colMul+colAdd) [+ col (n*colMul+colAdd2)]
__global__ void prep_wgen(const float* __restrict__ W, int srcN, int dstOff,
                          int nValid, int colMul, int colAdd, int colAdd2) {
    __shared__ float tile[32][33];
    int tx = threadIdx.x, ty = threadIdx.y;   // (32, 8)
    int n = blockIdx.x * 32 + tx;
    #pragma unroll
    for (int i = 0; i < 4; i++) {
        int k = blockIdx.y * 32 + ty + i * 8;
        float v = 0.f;
        if (n < nValid) {
            v = W[(size_t)k * srcN + n * colMul + colAdd];
            if (colAdd2 >= 0) v += W[(size_t)k * srcN + n * colMul + colAdd2];
        }
        tile[ty + i * 8][tx] = v;
    }
    __syncthreads();
    #pragma unroll
    for (int i = 0; i < 4; i++) {
        int n2 = blockIdx.x * 32 + ty + i * 8;
        int k2 = blockIdx.y * 32 + tx;
        float v = tile[tx][ty + i * 8];
        __nv_bfloat16 hi = __float2bfloat16(v);
        __nv_bfloat16 lo = __float2bfloat16(v - __bfloat162float(hi));
        __nv_bfloat16* row = g_Bp + (size_t)(dstOff + n2) * KP;
        row[k2]        = hi;
        row[512 + k2]  = lo;
        row[1024 + k2] = hi;
    }
}

// ---------------- prep: packed planar bias ----------------
__global__ void prep_bias(const float* __restrict__ bsw, const float* __restrict__ bsmu,
                          const float* __restrict__ bsvar, const float* __restrict__ btw,
                          const float* __restrict__ btmu, const float* __restrict__ btvar) {
    int c = blockIdx.x * 128 + threadIdx.x;
    if (c >= NTOT) return;
    float v = 0.f;
    if (c < PS_MU)        { if (c < LL1) v = bsw[c]; }
    else if (c < PS_VAR)  { int n = c - PS_MU;  if (n < LL1) v = bsmu[n]; }
    else if (c < PT_W)    { int n = c - PS_VAR; if (n < LL1) v = bsvar[n]; }
    else if (c < PT_MU0)  { int n = c - PT_W;   if (n < LL2) v = btw[n]; }
    else if (c < PT_MU1)  { int n = c - PT_MU0; if (n < LL2) v = btmu[2 * n]; }
    else if (c < PT_D0)   { int n = c - PT_MU1; if (n < LL2) v = btmu[2 * n + 1]; }
    else if (c < PT_SUM)  { int n = c - PT_D0;  if (n < LL2) v = btvar[4 * n]; }
    else if (c < PT_D1)   { int n = c - PT_SUM; if (n < LL2) v = btvar[4 * n + 1] + btvar[4 * n + 2]; }
    else                  { int n = c - PT_D1;  if (n < LL2) v = btvar[4 * n + 3]; }
    g_bias[c] = v;
}

// ---------------- HMMA GEMM: 128x128 CTA, KC=64, 3-stage cp.async ----------
#define TILE_STRIDE 72
#define BUF_BYTES 36864
#define SMEM_BYTES (3*BUF_BYTES)   // 110592
#define STG_STRIDE 132

__device__ __forceinline__ void issue_tile(uint32_t dstBase,
                                           const __nv_bfloat16* __restrict__ src,
                                           int row0, int kc, int tid) {
    #pragma unroll
    for (int i = 0; i < 4; i++) {
        int ci  = i * 256 + tid;          // 0..1023
        int r   = ci >> 3;                // 0..127
        int c16 = ci & 7;
        uint32_t dst = dstBase + (uint32_t)(r * (TILE_STRIDE * 2) + c16 * 16);
        cp_async16(dst, src + (size_t)(row0 + r) * KP + kc + c16 * 8);
    }
}

__global__ void __launch_bounds__(256) gemm_tc()
{
    extern __shared__ char smem[];
    uint32_t sbase = smem_u32(smem);
    int tid = threadIdx.x, wid = tid >> 5, lane = tid & 31;
    int m0 = blockIdx.x * 128;
    int n0 = blockIdx.y * 128;

    int wm = (wid & 3) * 32;
    int wn = (wid >> 2) * 64;
    int lr = lane & 15;
    int lc = (lane >> 4) * 8;

    float acc[2][8][4];
    #pragma unroll
    for (int mi = 0; mi < 2; mi++)
        #pragma unroll
        for (int ni = 0; ni < 8; ni++)
            #pragma unroll
            for (int q = 0; q < 4; q++) acc[mi][ni][q] = 0.f;

    // prologue: chunks 0,1 -> bufs 0,1
    issue_tile(sbase, g_Ap, m0, 0, tid);
    issue_tile(sbase + 18432, g_Bp, n0, 0, tid);
    CP_COMMIT();
    issue_tile(sbase + BUF_BYTES, g_Ap, m0, KC, tid);
    issue_tile(sbase + BUF_BYTES + 18432, g_Bp, n0, KC, tid);
    CP_COMMIT();

    for (int c = 0; c < NCH; c++) {
        if (c + 1 < NCH) { CP_WAIT(1); } else { CP_WAIT(0); }
        __syncthreads();
        if (c + 2 < NCH) {
            uint32_t nb = sbase + (uint32_t)(((c + 2) % 3) * BUF_BYTES);
            issue_tile(nb, g_Ap, m0, (c + 2) * KC, tid);
            issue_tile(nb + 18432, g_Bp, n0, (c + 2) * KC, tid);
            CP_COMMIT();
        }
        uint32_t aBase = sbase + (uint32_t)((c % 3) * BUF_BYTES);
        uint32_t bBase = aBase + 18432;
        #pragma unroll
        for (int ks = 0; ks < 4; ks++) {
            uint32_t af[2][4];
            #pragma unroll
            for (int mi = 0; mi < 2; mi++)
                ldmx4(af[mi], aBase + (uint32_t)(((wm + mi * 16 + lr) * TILE_STRIDE
                                                  + ks * 16 + lc) * 2));
            uint32_t bf[4][4];
            #pragma unroll
            for (int nb = 0; nb < 4; nb++)
                ldmx4(bf[nb], bBase + (uint32_t)(((wn + nb * 16 + lr) * TILE_STRIDE
                                                  + ks * 16 + lc) * 2));
            #pragma unroll
            for (int mi = 0; mi < 2; mi++)
                #pragma unroll
                for (int nb = 0; nb < 4; nb++) {
                    mma16816(acc[mi][nb * 2 + 0], af[mi], bf[nb][0], bf[nb][2]);
                    mma16816(acc[mi][nb * 2 + 1], af[mi], bf[nb][1], bf[nb][3]);
                }
        }
        __syncthreads();
    }
    // last chunk used buf 2 (bytes 73728+); staging uses bytes [0, 67584) — disjoint.

    float* stage = (float*)smem;
    int gr = lane >> 2;
    int gc = (lane & 3) * 2;
    #pragma unroll
    for (int mi = 0; mi < 2; mi++)
        #pragma unroll
        for (int ni = 0; ni < 8; ni++) {
            int row = wm + mi * 16 + gr;
            int col = wn + ni * 8 + gc;
            *(float2*)&stage[row * STG_STRIDE + col] =
                make_float2(acc[mi][ni][0], acc[mi][ni][1]);
            *(float2*)&stage[(row + 8) * STG_STRIDE + col] =
                make_float2(acc[mi][ni][2], acc[mi][ni][3]);
        }
    __syncthreads();

    bool isv = (n0 == PS_VAR);   // s_var plane: apply exp(clip(.))
    for (int i = tid; i < 128 * 32; i += 256) {
        int row = i >> 5, q = i & 31;
        int col = q * 4;
        float4 b4 = *(const float4*)&g_bias[n0 + col];
        const float* s = &stage[row * STG_STRIDE + col];
        float4 v = make_float4(s[0] + b4.x, s[1] + b4.y, s[2] + b4.z, s[3] + b4.w);
        if (isv) {
            v.x = __expf(fminf(fmaxf(v.x, -1.f), 1.f));
            v.y = __expf(fminf(fmaxf(v.y, -1.f), 1.f));
            v.z = __expf(fminf(fmaxf(v.z, -1.f), 1.f));
            v.w = __expf(fminf(fmaxf(v.w, -1.f), 1.f));
        }
        *(float4*)&g_C[(size_t)(m0 + row) * NTOT + n0 + col] = v;
    }
}

// ---------------- scan ----------------
__device__ __forceinline__ float tanh_acc(float x) {
    float xc = fminf(fmaxf(x, -15.f), 15.f);
    float e = __expf(2.f * xc);
    return __fdividef(e - 1.f, e + 1.f);
}

struct Step { float sw, smu, svar, tw, m0, m1, r0, rs, r1; };

__device__ __forceinline__ Step load_step(int row, int chain, int j) {
    const float* base = g_C + (size_t)row * NTOT;
    Step s;
    s.sw   = base[PS_W   + j];
    s.smu  = base[PS_MU  + j];
    s.svar = base[PS_VAR + j];
    s.tw   = base[PT_W   + chain];
    s.m0   = base[PT_MU0 + chain];
    s.m1   = base[PT_MU1 + chain];
    s.r0   = base[PT_D0  + chain];
    s.rs   = base[PT_SUM + chain];
    s.r1   = base[PT_D1  + chain];
    return s;
}

__device__ __forceinline__ void transform_t(const Step& s,
                                            float& v00, float& v01, float& v11) {
    float d0 = __expf(fminf(fmaxf(s.r0, -1.f), 1.f));
    float d1 = __expf(fminf(fmaxf(s.r1, -1.f), 1.f));
    v00 = d0; v11 = d1;
    v01 = 0.9f * tanh_acc(0.5f * s.rs) * sqrtf(d0 * d1);
}

__device__ __forceinline__ void merge2x2(
    float tmu0, float tmu1, float tv00, float tv01, float tv11,
    float nmu, float nvar, bool child,
    float& zeta, float& mu_new, float& var_new)
{
    float det  = tv00 * tv11 - tv01 * tv01;
    float idet = __fdividef(1.f, det);
    float a  = tv11 * idet;
    float bo = -tv01 * idet;
    float dd = tv00 * idet;
    float e0 = a  * tmu0 + bo * tmu1;
    float e1 = bo * tmu0 + dd * tmu1;
    float quad1 = e0 * e0 * tv00 + 2.f * e0 * e1 * tv01 + e1 * e1 * tv11;
    float zeta1 = -0.5f * (2.f * LOG2PI + __logf(det) + quad1);
    float l2   = __fdividef(1.f, nvar);
    float eta2 = nmu * l2;
    float zeta2 = -0.5f * (LOG2PI + __logf(nvar) + nmu * nmu * l2);
    float den, keep, es, la, iden;
    if (child) { den = dd + l2; iden = __fdividef(1.f, den); keep = e0; es = e1 + eta2; la = a  - bo * bo * iden; }
    else       { den = a  + l2; iden = __fdividef(1.f, den); keep = e1; es = e0 + eta2; la = dd - bo * bo * iden; }
    float eta_new = keep - bo * iden * es;
    var_new = __fdividef(1.f, la);
    mu_new  = var_new * eta_new;
    float zm = -0.5f * (LOG2PI - __logf(den) + es * es * iden);
    float zn = -0.5f * (LOG2PI - __logf(la)  + eta_new * eta_new * var_new);
    zeta = zeta1 + zeta2 - zm - zn;
}

__global__ __launch_bounds__(256) void scan_kernel(float* __restrict__ out)
{
    int chain = blockIdx.x * blockDim.x + threadIdx.x;
    if (chain >= LL2) return;
    int b = blockIdx.y;
    int j = chain % LL1;
    int row0 = b * TT;

    Step s0 = load_step(row0, chain, j);
    Step s1 = load_step(row0 + 1, chain, j);

    // t = 0
    float v00, v01, v11;
    transform_t(s0, v00, v01, v11);
    float sc0, mu_c, var_c;
    merge2x2(s0.m0, s0.m1, v00, v01, v11, s0.smu, s0.svar, true, sc0, mu_c, var_c);

    float u00, u01, u11;
    transform_t(s1, u00, u01, u11);
    float sp0, mu_p, var_p;
    merge2x2(s1.m0, s1.m1, u00, u01, u11, mu_c, var_c, false, sp0, mu_p, var_p);

    out[(size_t)row0 * LL2 + chain] = sc0 + sp0 + s0.tw + s0.sw;

    // t = 1..T-1 (prefetch next row while computing current)
    Step cur = s1;
    for (int t = 1; t < TT; t++) {
        Step nxt;
        if (t + 1 < TT) nxt = load_step(row0 + t + 1, chain, j);

        float w00, w01, w11;
        transform_t(cur, w00, w01, w11);

        float vsum = var_p + cur.svar;
        float logv = __logf(vsum);
        float inv  = __fdividef(1.f, vsum);
        float diff = mu_p - cur.smu;
        float scale_c = -0.5f * (LOG2PI + logv + diff * diff * inv);
        float mu_c2  = (mu_p * cur.svar + cur.smu * var_p) * inv;
        float var_c2 = vsum - 0.5f * logv;

        float scale_p, mu_n, var_n;
        merge2x2(cur.m0, cur.m1, w00, w01, w11, mu_c2, var_c2, false, scale_p, mu_n, var_n);
        mu_p = mu_n; var_p = var_n;

        out[(size_t)(row0 + t) * LL2 + chain] = scale_c + scale_p + cur.tw + cur.sw;
        cur = nxt;
    }
}

// ---------------- launch ----------------
extern "C" void kernel_launch(void* const* d_in, const int* in_sizes, int n_in,
                              void* d_out, int out_size)
{
    const float* x      = (const float*)d_in[0];
    const float* Ws_w   = (const float*)d_in[1];
    const float* bs_w   = (const float*)d_in[2];
    const float* Ws_mu  = (const float*)d_in[3];
    const float* bs_mu  = (const float*)d_in[4];
    const float* Ws_var = (const float*)d_in[5];
    const float* bs_var = (const float*)d_in[6];
    const float* Wt_w   = (const float*)d_in[7];
    const float* bt_w   = (const float*)d_in[8];
    const float* Wt_mu  = (const float*)d_in[9];
    const float* bt_mu  = (const float*)d_in[10];
    const float* Wt_var = (const float*)d_in[11];
    const float* bt_var = (const float*)d_in[12];
    float* out = (float*)d_out;

    cudaFuncSetAttribute(gemm_tc, cudaFuncAttributeMaxDynamicSharedMemorySize, SMEM_BYTES);

    prep_x<<<(MM * DD) / 256, 256>>>(x);
    prep_bias<<<NTILES, 128>>>(bs_w, bs_mu, bs_var, bt_w, bt_mu, bt_var);

    dim3 wblk(32, 8);
    prep_wgen<<<dim3(128  / 32, 16), wblk>>>(Ws_w,   LL1,     PS_W,   LL1, 1, 0, -1);
    prep_wgen<<<dim3(128  / 32, 16), wblk>>>(Ws_mu,  LL1,     PS_MU,  LL1, 1, 0, -1);
    prep_wgen<<<dim3(128  / 32, 16), wblk>>>(Ws_var, LL1,     PS_VAR, LL1, 1, 0, -1);
    prep_wgen<<<dim3(NP_CH / 32, 16), wblk>>>(Wt_w,   LL2,     PT_W,   LL2, 1, 0, -1);
    prep_wgen<<<dim3(NP_CH / 32, 16), wblk>>>(Wt_mu,  LL2 * 2, PT_MU0, LL2, 2, 0, -1);
    prep_wgen<<<dim3(NP_CH / 32, 16), wblk>>>(Wt_mu,  LL2 * 2, PT_MU1, LL2, 2, 1, -1);
    prep_wgen<<<dim3(NP_CH / 32, 16), wblk>>>(Wt_var, LL2 * 4, PT_D0,  LL2, 4, 0, -1);
    prep_wgen<<<dim3(NP_CH / 32, 16), wblk>>>(Wt_var, LL2 * 4, PT_SUM, LL2, 4, 1, 2);
    prep_wgen<<<dim3(NP_CH / 32, 16), wblk>>>(Wt_var, LL2 * 4, PT_D1,  LL2, 4, 3, -1);

    gemm_tc<<<dim3(32, NTILES), 256, SMEM_BYTES>>>();

    scan_kernel<<<dim3((LL2 + 255) / 256, BB), 256>>>(out);
}